// round 5
// baseline (speedup 1.0000x reference)
#include <cuda_runtime.h>

#define F 128
#define N_MAX 100352
#define E_MAX 1600000
#define TNODES 8

// Scratch (device globals — allocation-free per harness rules)
__device__ float g_W[F * F];
__device__ float g_dinv[N_MAX];
__device__ int   g_count[N_MAX];
__device__ int   g_offset[N_MAX];
__device__ int   g_cursor[N_MAX];
__device__ int   g_bsum[(N_MAX + 255) / 256];
__device__ int   g_srow[E_MAX];
__device__ float g_scoef[E_MAX];

// ---------------------------------------------------------------------------
// Packed fp32x2 helpers (sm_103a dual-lane fp32 pipe; full fp32 numerics)
// ---------------------------------------------------------------------------
__device__ __forceinline__ unsigned long long ffma2(unsigned long long a,
                                                    unsigned long long b,
                                                    unsigned long long c) {
    unsigned long long r;
    asm("fma.rn.f32x2 %0, %1, %2, %3;" : "=l"(r) : "l"(a), "l"(b), "l"(c));
    return r;
}
__device__ __forceinline__ unsigned long long pack2(float x) {
    unsigned long long r;
    asm("mov.b64 %0, {%1, %1};" : "=l"(r) : "f"(x));
    return r;
}
__device__ __forceinline__ float2 unpack2(unsigned long long v) {
    float2 f;
    asm("mov.b64 {%0, %1}, %2;" : "=f"(f.x), "=f"(f.y) : "l"(v));
    return f;
}

// ---------------------------------------------------------------------------
// K1: evolve weight — one GRU step on W0 (batch = F rows).
// ---------------------------------------------------------------------------
__global__ void evolve_kernel(const float* __restrict__ W0,
                              const float* __restrict__ w_ih,
                              const float* __restrict__ w_hh,
                              const float* __restrict__ b_ih,
                              const float* __restrict__ b_hh) {
    __shared__ float s_row[F];
    __shared__ float s_gi[3 * F];
    __shared__ float s_gh[3 * F];
    int i = blockIdx.x;
    int j = threadIdx.x;  // 0..383
    if (j < F) s_row[j] = W0[i * F + j];
    __syncthreads();

    float gi = b_ih[j], gh = b_hh[j];
    const float* wi = w_ih + j * F;
    const float* wh = w_hh + j * F;
#pragma unroll 8
    for (int k = 0; k < F; k++) {
        float a = s_row[k];
        gi += a * wi[k];
        gh += a * wh[k];
    }
    s_gi[j] = gi;
    s_gh[j] = gh;
    __syncthreads();

    if (j < F) {
        float r = 1.f / (1.f + expf(-(s_gi[j] + s_gh[j])));
        float z = 1.f / (1.f + expf(-(s_gi[F + j] + s_gh[F + j])));
        float nn = tanhf(s_gi[2 * F + j] + r * s_gh[2 * F + j]);
        g_W[i * F + j] = (1.f - z) * nn + z * s_row[j];
    }
}

// ---------------------------------------------------------------------------
// K2: init deg (self loop weight 1) and histogram counters
// ---------------------------------------------------------------------------
__global__ void init_kernel(int n) {
    int i = blockIdx.x * blockDim.x + threadIdx.x;
    if (i < n) { g_dinv[i] = 1.0f; g_count[i] = 0; }
}

// K3: degree accumulation + target histogram in one pass
__global__ void deg_hist(const int* __restrict__ ei, const float* __restrict__ ew, int E) {
    int e = blockIdx.x * blockDim.x + threadIdx.x;
    if (e < E) {
        int c = ei[E + e];
        atomicAdd(&g_dinv[c], ew[e]);
        atomicAdd(&g_count[c], 1);
    }
}

// ---------------------------------------------------------------------------
// K4-K6: dinv finish (fused) + exclusive scan of g_count -> g_offset/g_cursor
// ---------------------------------------------------------------------------
__global__ void scan_part(int n) {
    __shared__ int s[256];
    int i = blockIdx.x * 256 + threadIdx.x;
    if (i < n) g_dinv[i] = rsqrtf(g_dinv[i]);  // deg >= 1 always (fused deg_finish)
    s[threadIdx.x] = (i < n) ? g_count[i] : 0;
    __syncthreads();
    for (int st = 128; st; st >>= 1) {
        if (threadIdx.x < st) s[threadIdx.x] += s[threadIdx.x + st];
        __syncthreads();
    }
    if (threadIdx.x == 0) g_bsum[blockIdx.x] = s[0];
}

__global__ void scan_top(int nb) {
    if (threadIdx.x == 0) {
        int run = 0;
        for (int b = 0; b < nb; b++) {
            int v = g_bsum[b];
            g_bsum[b] = run;
            run += v;
        }
    }
}

__global__ void scan_final(int n) {
    __shared__ int s[257];
    int i = blockIdx.x * 256 + threadIdx.x;
    int v = (i < n) ? g_count[i] : 0;
    s[threadIdx.x + 1] = v;
    if (threadIdx.x == 0) s[0] = 0;
    __syncthreads();
    for (int st = 1; st < 256; st <<= 1) {
        int add = (threadIdx.x >= st) ? s[threadIdx.x - st] : 0;
        __syncthreads();
        s[threadIdx.x] += add;
        __syncthreads();
    }
    if (i < n) {
        int off = g_bsum[blockIdx.x] + s[threadIdx.x];
        g_offset[i] = off;
        g_cursor[i] = off;
    }
}

// ---------------------------------------------------------------------------
// K7: place edges into target-sorted order with precomputed coefficients
// ---------------------------------------------------------------------------
__global__ void place_kernel(const int* __restrict__ ei, const float* __restrict__ ew, int E) {
    int e = blockIdx.x * blockDim.x + threadIdx.x;
    if (e >= E) return;
    int r = ei[e];
    int c = ei[E + e];
    int p = atomicAdd(&g_cursor[c], 1);
    g_srow[p] = r;
    g_scoef[p] = g_dinv[r] * ew[e] * g_dinv[c];
}

// ---------------------------------------------------------------------------
// K8: FUSED aggregate + GEMM + epilogue.
// Block = 256 threads (8 warps) = 64 nodes. Phase 1: warp-per-node gather
// straight into smem staging (no g_agg round trip). Phase 2: f32x2 GEMM,
// relu, dot lin_w, store one float per node.
// ---------------------------------------------------------------------------
__global__ void fused_kernel(const float* __restrict__ x,
                             const float* __restrict__ lin_w,
                             const float* __restrict__ lin_b,
                             float* __restrict__ out, int n) {
    extern __shared__ float smem[];
    float* sW = smem;                 // F*F = 16384
    float* sLin = smem + F * F;       // F
    float* sAgg = sLin + F;           // 64 * F = 8192

    int tid = threadIdx.x;  // 256
    // Start W load first so it overlaps the gather phase
    for (int i = tid; i < F * F / 4; i += blockDim.x)
        ((float4*)sW)[i] = ((const float4*)g_W)[i];
    if (tid < F) sLin[tid] = lin_w[tid];

    int warp = tid >> 5, lane = tid & 31;
    int node0 = blockIdx.x * 64 + warp * TNODES;
    float* sa = sAgg + warp * (TNODES * F);

    // ---- Phase 1: gather-aggregate TNODES nodes per warp ----
#pragma unroll 1
    for (int nn = 0; nn < TNODES; nn++) {
        int node = node0 + nn;
        float4 acc = make_float4(0.f, 0.f, 0.f, 0.f);
        if (node < n) {
            int off = g_offset[node];
            int cnt = g_count[node];
            float dc = g_dinv[node];
            float sc = dc * dc;

            acc = ((const float4*)x)[(size_t)node * 32 + lane];
            acc.x *= sc; acc.y *= sc; acc.z *= sc; acc.w *= sc;

            for (int base = 0; base < cnt; base += 32) {
                int m = min(32, cnt - base);
                int r_l = 0; float cf_l = 0.f;
                if (lane < m) {
                    r_l = __ldg(&g_srow[off + base + lane]);
                    cf_l = __ldg(&g_scoef[off + base + lane]);
                }
                for (int j = 0; j < m; j++) {
                    int r = __shfl_sync(0xffffffffu, r_l, j);
                    float cf = __shfl_sync(0xffffffffu, cf_l, j);
                    float4 xv = ((const float4*)x)[(size_t)r * 32 + lane];
                    acc.x += cf * xv.x;
                    acc.y += cf * xv.y;
                    acc.z += cf * xv.z;
                    acc.w += cf * xv.w;
                }
            }
        }
        ((float4*)(sa + nn * F))[lane] = acc;
    }
    __syncthreads();  // covers sW/sLin loads and all warps' sAgg writes

    // ---- Phase 2: GEMM + relu + linear (packed f32x2) ----
    unsigned long long acc2[TNODES][2];
#pragma unroll
    for (int nn = 0; nn < TNODES; nn++) { acc2[nn][0] = 0ULL; acc2[nn][1] = 0ULL; }

    int col = lane * 4;
    for (int k0 = 0; k0 < F; k0 += 4) {
        ulonglong2 w0 = *(const ulonglong2*)&sW[(k0 + 0) * F + col];
        ulonglong2 w1 = *(const ulonglong2*)&sW[(k0 + 1) * F + col];
        ulonglong2 w2 = *(const ulonglong2*)&sW[(k0 + 2) * F + col];
        ulonglong2 w3 = *(const ulonglong2*)&sW[(k0 + 3) * F + col];
#pragma unroll
        for (int nn = 0; nn < TNODES; nn++) {
            float4 a = *(const float4*)&sa[nn * F + k0];
            unsigned long long ax = pack2(a.x), ay = pack2(a.y),
                               az = pack2(a.z), aw = pack2(a.w);
            acc2[nn][0] = ffma2(ax, w0.x, acc2[nn][0]);
            acc2[nn][0] = ffma2(ay, w1.x, acc2[nn][0]);
            acc2[nn][0] = ffma2(az, w2.x, acc2[nn][0]);
            acc2[nn][0] = ffma2(aw, w3.x, acc2[nn][0]);
            acc2[nn][1] = ffma2(ax, w0.y, acc2[nn][1]);
            acc2[nn][1] = ffma2(ay, w1.y, acc2[nn][1]);
            acc2[nn][1] = ffma2(az, w2.y, acc2[nn][1]);
            acc2[nn][1] = ffma2(aw, w3.y, acc2[nn][1]);
        }
    }

    float lw0 = sLin[col], lw1 = sLin[col + 1], lw2 = sLin[col + 2], lw3 = sLin[col + 3];
    float bias = lin_b[0];
#pragma unroll
    for (int nn = 0; nn < TNODES; nn++) {
        float2 h01 = unpack2(acc2[nn][0]);
        float2 h23 = unpack2(acc2[nn][1]);
        float s = fmaxf(h01.x, 0.f) * lw0 + fmaxf(h01.y, 0.f) * lw1 +
                  fmaxf(h23.x, 0.f) * lw2 + fmaxf(h23.y, 0.f) * lw3;
#pragma unroll
        for (int off = 16; off; off >>= 1)
            s += __shfl_xor_sync(0xffffffffu, s, off);
        int node = node0 + nn;
        if (lane == 0 && node < n) out[node] = s + bias;
    }
}

// ---------------------------------------------------------------------------
extern "C" void kernel_launch(void* const* d_in, const int* in_sizes, int n_in,
                              void* d_out, int out_size) {
    const float* x     = (const float*)d_in[0];
    const int*   ei    = (const int*)d_in[1];
    const float* ew    = (const float*)d_in[2];
    const float* W0    = (const float*)d_in[3];
    const float* w_ih  = (const float*)d_in[4];
    const float* w_hh  = (const float*)d_in[5];
    const float* b_ih  = (const float*)d_in[6];
    const float* b_hh  = (const float*)d_in[7];
    const float* lin_w = (const float*)d_in[8];
    const float* lin_b = (const float*)d_in[9];
    float* out = (float*)d_out;

    int n = in_sizes[0] / F;
    int E = in_sizes[2];
    int nb = (n + 255) / 256;

    evolve_kernel<<<F, 3 * F>>>(W0, w_ih, w_hh, b_ih, b_hh);
    init_kernel<<<nb, 256>>>(n);
    deg_hist<<<(E + 255) / 256, 256>>>(ei, ew, E);
    scan_part<<<nb, 256>>>(n);          // also finishes dinv
    scan_top<<<1, 32>>>(nb);
    scan_final<<<nb, 256>>>(n);
    place_kernel<<<(E + 255) / 256, 256>>>(ei, ew, E);

    int blocks = (n + 63) / 64;
    size_t smem = (size_t)(F * F + F + 64 * F) * sizeof(float);  // 98816 B
    cudaFuncSetAttribute(fused_kernel, cudaFuncAttributeMaxDynamicSharedMemorySize, (int)smem);
    fused_kernel<<<blocks, 256, smem>>>(x, lin_w, lin_b, out, n);
}

// round 6
// speedup vs baseline: 1.0533x; 1.0533x over previous
#include <cuda_runtime.h>

#define F 128
#define N_MAX 100352
#define E_MAX 1600000
#define TNODES 8

// Scratch (device globals — allocation-free per harness rules)
__device__ float g_W[F * F];
__device__ float g_dinv[N_MAX];
__device__ int   g_count[N_MAX];
__device__ int   g_offset[N_MAX];
__device__ int   g_cursor[N_MAX];
__device__ int   g_bsum[(N_MAX + 255) / 256];
__device__ int   g_srow[E_MAX];
__device__ float g_scoef[E_MAX];
__device__ float g_agg[(size_t)N_MAX * F];

// ---------------------------------------------------------------------------
// Packed fp32x2 helpers (sm_103a dual-lane fp32 pipe; full fp32 numerics)
// ---------------------------------------------------------------------------
__device__ __forceinline__ unsigned long long ffma2(unsigned long long a,
                                                    unsigned long long b,
                                                    unsigned long long c) {
    unsigned long long r;
    asm("fma.rn.f32x2 %0, %1, %2, %3;" : "=l"(r) : "l"(a), "l"(b), "l"(c));
    return r;
}
__device__ __forceinline__ unsigned long long pack2(float x) {
    unsigned long long r;
    asm("mov.b64 %0, {%1, %1};" : "=l"(r) : "f"(x));
    return r;
}
__device__ __forceinline__ float2 unpack2(unsigned long long v) {
    float2 f;
    asm("mov.b64 {%0, %1}, %2;" : "=f"(f.x), "=f"(f.y) : "l"(v));
    return f;
}

// ---------------------------------------------------------------------------
// K1: evolve weight — one GRU step on W0 (batch = F rows).
// ---------------------------------------------------------------------------
__global__ void evolve_kernel(const float* __restrict__ W0,
                              const float* __restrict__ w_ih,
                              const float* __restrict__ w_hh,
                              const float* __restrict__ b_ih,
                              const float* __restrict__ b_hh) {
    __shared__ float s_row[F];
    __shared__ float s_gi[3 * F];
    __shared__ float s_gh[3 * F];
    int i = blockIdx.x;
    int j = threadIdx.x;  // 0..383
    if (j < F) s_row[j] = W0[i * F + j];
    __syncthreads();

    float gi = b_ih[j], gh = b_hh[j];
    const float* wi = w_ih + j * F;
    const float* wh = w_hh + j * F;
#pragma unroll 8
    for (int k = 0; k < F; k++) {
        float a = s_row[k];
        gi += a * wi[k];
        gh += a * wh[k];
    }
    s_gi[j] = gi;
    s_gh[j] = gh;
    __syncthreads();

    if (j < F) {
        float r = 1.f / (1.f + expf(-(s_gi[j] + s_gh[j])));
        float z = 1.f / (1.f + expf(-(s_gi[F + j] + s_gh[F + j])));
        float nn = tanhf(s_gi[2 * F + j] + r * s_gh[2 * F + j]);
        g_W[i * F + j] = (1.f - z) * nn + z * s_row[j];
    }
}

// ---------------------------------------------------------------------------
// K2: init deg (self loop weight 1) and histogram counters
// ---------------------------------------------------------------------------
__global__ void init_kernel(int n) {
    int i = blockIdx.x * blockDim.x + threadIdx.x;
    if (i < n) { g_dinv[i] = 1.0f; g_count[i] = 0; }
}

// K3: degree accumulation + target histogram in one pass
__global__ void deg_hist(const int* __restrict__ ei, const float* __restrict__ ew, int E) {
    int e = blockIdx.x * blockDim.x + threadIdx.x;
    if (e < E) {
        int c = ei[E + e];
        atomicAdd(&g_dinv[c], ew[e]);
        atomicAdd(&g_count[c], 1);
    }
}

// ---------------------------------------------------------------------------
// K4-K6: dinv finish (fused) + exclusive scan of g_count -> g_offset/g_cursor
// ---------------------------------------------------------------------------
__global__ void scan_part(int n) {
    __shared__ int s[256];
    int i = blockIdx.x * 256 + threadIdx.x;
    if (i < n) g_dinv[i] = rsqrtf(g_dinv[i]);  // deg >= 1 always (fused deg_finish)
    s[threadIdx.x] = (i < n) ? g_count[i] : 0;
    __syncthreads();
    for (int st = 128; st; st >>= 1) {
        if (threadIdx.x < st) s[threadIdx.x] += s[threadIdx.x + st];
        __syncthreads();
    }
    if (threadIdx.x == 0) g_bsum[blockIdx.x] = s[0];
}

__global__ void scan_top(int nb) {
    if (threadIdx.x == 0) {
        int run = 0;
        for (int b = 0; b < nb; b++) {
            int v = g_bsum[b];
            g_bsum[b] = run;
            run += v;
        }
    }
}

__global__ void scan_final(int n) {
    __shared__ int s[257];
    int i = blockIdx.x * 256 + threadIdx.x;
    int v = (i < n) ? g_count[i] : 0;
    s[threadIdx.x + 1] = v;
    if (threadIdx.x == 0) s[0] = 0;
    __syncthreads();
    for (int st = 1; st < 256; st <<= 1) {
        int add = (threadIdx.x >= st) ? s[threadIdx.x - st] : 0;
        __syncthreads();
        s[threadIdx.x] += add;
        __syncthreads();
    }
    if (i < n) {
        int off = g_bsum[blockIdx.x] + s[threadIdx.x];
        g_offset[i] = off;
        g_cursor[i] = off;
    }
}

// ---------------------------------------------------------------------------
// K7: place edges into target-sorted order with precomputed coefficients
// ---------------------------------------------------------------------------
__global__ void place_kernel(const int* __restrict__ ei, const float* __restrict__ ew, int E) {
    int e = blockIdx.x * blockDim.x + threadIdx.x;
    if (e >= E) return;
    int r = ei[e];
    int c = ei[E + e];
    int p = atomicAdd(&g_cursor[c], 1);
    g_srow[p] = r;
    g_scoef[p] = g_dinv[r] * ew[e] * g_dinv[c];
}

// ---------------------------------------------------------------------------
// K8: aggregate — warp per node, MLP-4 pipelined gather.
// Lanes batch-load up to 32 edge records, shuffle-broadcast 4 at a time and
// issue 4 independent 16B gathers before consuming them.
// ---------------------------------------------------------------------------
__global__ void agg_kernel(const float* __restrict__ x, int n) {
    int gw = (int)((blockIdx.x * (unsigned)blockDim.x + threadIdx.x) >> 5);
    int lane = threadIdx.x & 31;
    if (gw >= n) return;

    int off = g_offset[gw];
    int cnt = g_count[gw];
    float dc = g_dinv[gw];
    float sc = dc * dc;

    float4 acc = ((const float4*)x)[(size_t)gw * 32 + lane];
    acc.x *= sc; acc.y *= sc; acc.z *= sc; acc.w *= sc;

    const float4* x4 = (const float4*)x;

    for (int base = 0; base < cnt; base += 32) {
        int m = min(32, cnt - base);
        int r_l = 0; float cf_l = 0.f;
        if (lane < m) {
            r_l = __ldg(&g_srow[off + base + lane]);
            cf_l = __ldg(&g_scoef[off + base + lane]);
        }
        int j = 0;
        for (; j + 4 <= m; j += 4) {
            int r0 = __shfl_sync(0xffffffffu, r_l, j + 0);
            int r1 = __shfl_sync(0xffffffffu, r_l, j + 1);
            int r2 = __shfl_sync(0xffffffffu, r_l, j + 2);
            int r3 = __shfl_sync(0xffffffffu, r_l, j + 3);
            float c0 = __shfl_sync(0xffffffffu, cf_l, j + 0);
            float c1 = __shfl_sync(0xffffffffu, cf_l, j + 1);
            float c2 = __shfl_sync(0xffffffffu, cf_l, j + 2);
            float c3 = __shfl_sync(0xffffffffu, cf_l, j + 3);
            // 4 independent gathers in flight
            float4 v0 = x4[(size_t)r0 * 32 + lane];
            float4 v1 = x4[(size_t)r1 * 32 + lane];
            float4 v2 = x4[(size_t)r2 * 32 + lane];
            float4 v3 = x4[(size_t)r3 * 32 + lane];
            acc.x += c0 * v0.x; acc.y += c0 * v0.y; acc.z += c0 * v0.z; acc.w += c0 * v0.w;
            acc.x += c1 * v1.x; acc.y += c1 * v1.y; acc.z += c1 * v1.z; acc.w += c1 * v1.w;
            acc.x += c2 * v2.x; acc.y += c2 * v2.y; acc.z += c2 * v2.z; acc.w += c2 * v2.w;
            acc.x += c3 * v3.x; acc.y += c3 * v3.y; acc.z += c3 * v3.z; acc.w += c3 * v3.w;
        }
        for (; j < m; j++) {
            int r = __shfl_sync(0xffffffffu, r_l, j);
            float cf = __shfl_sync(0xffffffffu, cf_l, j);
            float4 xv = x4[(size_t)r * 32 + lane];
            acc.x += cf * xv.x;
            acc.y += cf * xv.y;
            acc.z += cf * xv.z;
            acc.w += cf * xv.w;
        }
    }
    ((float4*)g_agg)[(size_t)gw * 32 + lane] = acc;
}

// ---------------------------------------------------------------------------
// K9: fused out = relu(agg @ W) . lin_w + lin_b — packed f32x2 FMA.
// ---------------------------------------------------------------------------
__global__ void final_kernel(const float* __restrict__ lin_w, const float* __restrict__ lin_b,
                             float* __restrict__ out, int n) {
    extern __shared__ float smem[];
    float* sW = smem;                 // F*F
    float* sLin = smem + F * F;       // F
    float* sAgg = sLin + F;           // 8 warps * TNODES * F

    int tid = threadIdx.x;  // 256
    for (int i = tid; i < F * F / 4; i += blockDim.x)
        ((float4*)sW)[i] = ((const float4*)g_W)[i];
    if (tid < F) sLin[tid] = lin_w[tid];
    __syncthreads();

    int warp = tid >> 5, lane = tid & 31;
    int node0 = (blockIdx.x * 8 + warp) * TNODES;
    float* sa = sAgg + warp * (TNODES * F);

#pragma unroll
    for (int nn = 0; nn < TNODES; nn++) {
        int node = node0 + nn;
        float4 v = make_float4(0.f, 0.f, 0.f, 0.f);
        if (node < n) v = ((const float4*)g_agg)[(size_t)node * 32 + lane];
        ((float4*)(sa + nn * F))[lane] = v;
    }
    __syncwarp();

    unsigned long long acc[TNODES][2];
#pragma unroll
    for (int nn = 0; nn < TNODES; nn++) { acc[nn][0] = 0ULL; acc[nn][1] = 0ULL; }

    int col = lane * 4;
    for (int k0 = 0; k0 < F; k0 += 4) {
        ulonglong2 w0 = *(const ulonglong2*)&sW[(k0 + 0) * F + col];
        ulonglong2 w1 = *(const ulonglong2*)&sW[(k0 + 1) * F + col];
        ulonglong2 w2 = *(const ulonglong2*)&sW[(k0 + 2) * F + col];
        ulonglong2 w3 = *(const ulonglong2*)&sW[(k0 + 3) * F + col];
#pragma unroll
        for (int nn = 0; nn < TNODES; nn++) {
            float4 a = *(const float4*)&sa[nn * F + k0];
            unsigned long long ax = pack2(a.x), ay = pack2(a.y),
                               az = pack2(a.z), aw = pack2(a.w);
            acc[nn][0] = ffma2(ax, w0.x, acc[nn][0]);
            acc[nn][0] = ffma2(ay, w1.x, acc[nn][0]);
            acc[nn][0] = ffma2(az, w2.x, acc[nn][0]);
            acc[nn][0] = ffma2(aw, w3.x, acc[nn][0]);
            acc[nn][1] = ffma2(ax, w0.y, acc[nn][1]);
            acc[nn][1] = ffma2(ay, w1.y, acc[nn][1]);
            acc[nn][1] = ffma2(az, w2.y, acc[nn][1]);
            acc[nn][1] = ffma2(aw, w3.y, acc[nn][1]);
        }
    }

    float lw0 = sLin[col], lw1 = sLin[col + 1], lw2 = sLin[col + 2], lw3 = sLin[col + 3];
    float bias = lin_b[0];
#pragma unroll
    for (int nn = 0; nn < TNODES; nn++) {
        float2 h01 = unpack2(acc[nn][0]);
        float2 h23 = unpack2(acc[nn][1]);
        float s = fmaxf(h01.x, 0.f) * lw0 + fmaxf(h01.y, 0.f) * lw1 +
                  fmaxf(h23.x, 0.f) * lw2 + fmaxf(h23.y, 0.f) * lw3;
#pragma unroll
        for (int off = 16; off; off >>= 1)
            s += __shfl_xor_sync(0xffffffffu, s, off);
        int node = node0 + nn;
        if (lane == 0 && node < n) out[node] = s + bias;
    }
}

// ---------------------------------------------------------------------------
extern "C" void kernel_launch(void* const* d_in, const int* in_sizes, int n_in,
                              void* d_out, int out_size) {
    const float* x     = (const float*)d_in[0];
    const int*   ei    = (const int*)d_in[1];
    const float* ew    = (const float*)d_in[2];
    const float* W0    = (const float*)d_in[3];
    const float* w_ih  = (const float*)d_in[4];
    const float* w_hh  = (const float*)d_in[5];
    const float* b_ih  = (const float*)d_in[6];
    const float* b_hh  = (const float*)d_in[7];
    const float* lin_w = (const float*)d_in[8];
    const float* lin_b = (const float*)d_in[9];
    float* out = (float*)d_out;

    int n = in_sizes[0] / F;
    int E = in_sizes[2];
    int nb = (n + 255) / 256;

    evolve_kernel<<<F, 3 * F>>>(W0, w_ih, w_hh, b_ih, b_hh);
    init_kernel<<<nb, 256>>>(n);
    deg_hist<<<(E + 255) / 256, 256>>>(ei, ew, E);
    scan_part<<<nb, 256>>>(n);          // also finishes dinv
    scan_top<<<1, 32>>>(nb);
    scan_final<<<nb, 256>>>(n);
    place_kernel<<<(E + 255) / 256, 256>>>(ei, ew, E);
    agg_kernel<<<(n * 32 + 255) / 256, 256>>>(x, n);  // warp per node

    int warps = (n + TNODES - 1) / TNODES;
    int blocks = (warps + 7) / 8;
    size_t smem = (size_t)(F * F + F + 8 * TNODES * F) * sizeof(float);
    cudaFuncSetAttribute(final_kernel, cudaFuncAttributeMaxDynamicSharedMemorySize, (int)smem);
    final_kernel<<<blocks, 256, smem>>>(lin_w, lin_b, out, n);
}

// round 7
// speedup vs baseline: 1.0769x; 1.0224x over previous
#include <cuda_runtime.h>
#include <cuda_fp16.h>

#define F 128
#define N_MAX 100352
#define E_MAX 1600000
#define TNODES 8

// Scratch (device globals — allocation-free per harness rules)
__device__ float g_W[F * F];
__device__ float g_dinv[N_MAX];
__device__ int   g_count[N_MAX];
__device__ int   g_offset[N_MAX];
__device__ int   g_cursor[N_MAX];
__device__ int   g_bsum[(N_MAX + 255) / 256];
__device__ unsigned long long g_edge[E_MAX];   // packed (row:int32 | coef:f32<<32)
__device__ __half g_xh[(size_t)N_MAX * F];     // fp16 copy of x for gather
__device__ float g_agg[(size_t)N_MAX * F];

// ---------------------------------------------------------------------------
// Packed fp32x2 helpers (sm_103a dual-lane fp32 pipe; full fp32 numerics)
// ---------------------------------------------------------------------------
__device__ __forceinline__ unsigned long long ffma2(unsigned long long a,
                                                    unsigned long long b,
                                                    unsigned long long c) {
    unsigned long long r;
    asm("fma.rn.f32x2 %0, %1, %2, %3;" : "=l"(r) : "l"(a), "l"(b), "l"(c));
    return r;
}
__device__ __forceinline__ unsigned long long pack2(float x) {
    unsigned long long r;
    asm("mov.b64 %0, {%1, %1};" : "=l"(r) : "f"(x));
    return r;
}
__device__ __forceinline__ float2 unpack2(unsigned long long v) {
    float2 f;
    asm("mov.b64 {%0, %1}, %2;" : "=f"(f.x), "=f"(f.y) : "l"(v));
    return f;
}

// ---------------------------------------------------------------------------
// K1: evolve weight — one GRU step on W0 (batch = F rows).
// ---------------------------------------------------------------------------
__global__ void evolve_kernel(const float* __restrict__ W0,
                              const float* __restrict__ w_ih,
                              const float* __restrict__ w_hh,
                              const float* __restrict__ b_ih,
                              const float* __restrict__ b_hh) {
    __shared__ float s_row[F];
    __shared__ float s_gi[3 * F];
    __shared__ float s_gh[3 * F];
    int i = blockIdx.x;
    int j = threadIdx.x;  // 0..383
    if (j < F) s_row[j] = W0[i * F + j];
    __syncthreads();

    float gi = b_ih[j], gh = b_hh[j];
    const float* wi = w_ih + j * F;
    const float* wh = w_hh + j * F;
#pragma unroll 8
    for (int k = 0; k < F; k++) {
        float a = s_row[k];
        gi += a * wi[k];
        gh += a * wh[k];
    }
    s_gi[j] = gi;
    s_gh[j] = gh;
    __syncthreads();

    if (j < F) {
        float r = 1.f / (1.f + expf(-(s_gi[j] + s_gh[j])));
        float z = 1.f / (1.f + expf(-(s_gi[F + j] + s_gh[F + j])));
        float nn = tanhf(s_gi[2 * F + j] + r * s_gh[2 * F + j]);
        g_W[i * F + j] = (1.f - z) * nn + z * s_row[j];
    }
}

// ---------------------------------------------------------------------------
// K2: x -> fp16 copy (for low-traffic gather)
// ---------------------------------------------------------------------------
__global__ void x2h_kernel(const float* __restrict__ x, int n) {
    int idx = blockIdx.x * blockDim.x + threadIdx.x;  // over n*32 float4s
    if (idx >= n * 32) return;
    float4 v = ((const float4*)x)[idx];
    __half2 a = __floats2half2_rn(v.x, v.y);
    __half2 b = __floats2half2_rn(v.z, v.w);
    uint2 o;
    o.x = *(unsigned int*)&a;
    o.y = *(unsigned int*)&b;
    ((uint2*)g_xh)[idx] = o;
}

// ---------------------------------------------------------------------------
// K3: init deg (self loop weight 1) and histogram counters
// ---------------------------------------------------------------------------
__global__ void init_kernel(int n) {
    int i = blockIdx.x * blockDim.x + threadIdx.x;
    if (i < n) { g_dinv[i] = 1.0f; g_count[i] = 0; }
}

// K4: degree accumulation + target histogram in one pass
__global__ void deg_hist(const int* __restrict__ ei, const float* __restrict__ ew, int E) {
    int e = blockIdx.x * blockDim.x + threadIdx.x;
    if (e < E) {
        int c = ei[E + e];
        atomicAdd(&g_dinv[c], ew[e]);
        atomicAdd(&g_count[c], 1);
    }
}

// ---------------------------------------------------------------------------
// K5-K7: dinv finish (fused) + exclusive scan of g_count -> g_offset/g_cursor
// ---------------------------------------------------------------------------
__global__ void scan_part(int n) {
    __shared__ int s[256];
    int i = blockIdx.x * 256 + threadIdx.x;
    if (i < n) g_dinv[i] = rsqrtf(g_dinv[i]);  // deg >= 1 always (fused deg_finish)
    s[threadIdx.x] = (i < n) ? g_count[i] : 0;
    __syncthreads();
    for (int st = 128; st; st >>= 1) {
        if (threadIdx.x < st) s[threadIdx.x] += s[threadIdx.x + st];
        __syncthreads();
    }
    if (threadIdx.x == 0) g_bsum[blockIdx.x] = s[0];
}

__global__ void scan_top(int nb) {
    if (threadIdx.x == 0) {
        int run = 0;
        for (int b = 0; b < nb; b++) {
            int v = g_bsum[b];
            g_bsum[b] = run;
            run += v;
        }
    }
}

__global__ void scan_final(int n) {
    __shared__ int s[257];
    int i = blockIdx.x * 256 + threadIdx.x;
    int v = (i < n) ? g_count[i] : 0;
    s[threadIdx.x + 1] = v;
    if (threadIdx.x == 0) s[0] = 0;
    __syncthreads();
    for (int st = 1; st < 256; st <<= 1) {
        int add = (threadIdx.x >= st) ? s[threadIdx.x - st] : 0;
        __syncthreads();
        s[threadIdx.x] += add;
        __syncthreads();
    }
    if (i < n) {
        int off = g_bsum[blockIdx.x] + s[threadIdx.x];
        g_offset[i] = off;
        g_cursor[i] = off;
    }
}

// ---------------------------------------------------------------------------
// K8: place edges into target-sorted order; one packed 8B record per edge
// ---------------------------------------------------------------------------
__global__ void place_kernel(const int* __restrict__ ei, const float* __restrict__ ew, int E) {
    int e = blockIdx.x * blockDim.x + threadIdx.x;
    if (e >= E) return;
    int r = ei[e];
    int c = ei[E + e];
    int p = atomicAdd(&g_cursor[c], 1);
    float cf = g_dinv[r] * ew[e] * g_dinv[c];
    g_edge[p] = (unsigned long long)(unsigned int)r |
                ((unsigned long long)__float_as_uint(cf) << 32);
}

// ---------------------------------------------------------------------------
// K9: aggregate — warp per node, fp16 gather (256B/edge), fp32 accumulate.
// Self-loop term uses exact fp32 x. MLP-4 pipelined inner loop.
// ---------------------------------------------------------------------------
__device__ __forceinline__ void acc_edge(float4& acc, float cf, uint2 v) {
    float2 a = __half22float2(*(__half2*)&v.x);
    float2 b = __half22float2(*(__half2*)&v.y);
    acc.x += cf * a.x;
    acc.y += cf * a.y;
    acc.z += cf * b.x;
    acc.w += cf * b.y;
}

__global__ void agg_kernel(const float* __restrict__ x, int n) {
    int gw = (int)((blockIdx.x * (unsigned)blockDim.x + threadIdx.x) >> 5);
    int lane = threadIdx.x & 31;
    if (gw >= n) return;

    int off = g_offset[gw];
    int cnt = g_count[gw];
    float dc = g_dinv[gw];
    float sc = dc * dc;

    float4 acc = ((const float4*)x)[(size_t)gw * 32 + lane];
    acc.x *= sc; acc.y *= sc; acc.z *= sc; acc.w *= sc;

    const uint2* x2 = (const uint2*)g_xh;  // row = 32 uint2 (128 halves)

    for (int base = 0; base < cnt; base += 32) {
        int m = min(32, cnt - base);
        unsigned long long rec = 0ULL;
        if (lane < m) rec = __ldg(&g_edge[off + base + lane]);
        int j = 0;
        for (; j + 4 <= m; j += 4) {
            unsigned long long q0 = __shfl_sync(0xffffffffu, rec, j + 0);
            unsigned long long q1 = __shfl_sync(0xffffffffu, rec, j + 1);
            unsigned long long q2 = __shfl_sync(0xffffffffu, rec, j + 2);
            unsigned long long q3 = __shfl_sync(0xffffffffu, rec, j + 3);
            int r0 = (int)(unsigned int)q0, r1 = (int)(unsigned int)q1;
            int r2 = (int)(unsigned int)q2, r3 = (int)(unsigned int)q3;
            float c0 = __uint_as_float((unsigned int)(q0 >> 32));
            float c1 = __uint_as_float((unsigned int)(q1 >> 32));
            float c2 = __uint_as_float((unsigned int)(q2 >> 32));
            float c3 = __uint_as_float((unsigned int)(q3 >> 32));
            // 4 independent 8B gathers in flight
            uint2 v0 = x2[(size_t)r0 * 32 + lane];
            uint2 v1 = x2[(size_t)r1 * 32 + lane];
            uint2 v2 = x2[(size_t)r2 * 32 + lane];
            uint2 v3 = x2[(size_t)r3 * 32 + lane];
            acc_edge(acc, c0, v0);
            acc_edge(acc, c1, v1);
            acc_edge(acc, c2, v2);
            acc_edge(acc, c3, v3);
        }
        for (; j < m; j++) {
            unsigned long long q = __shfl_sync(0xffffffffu, rec, j);
            int r = (int)(unsigned int)q;
            float cf = __uint_as_float((unsigned int)(q >> 32));
            uint2 v = x2[(size_t)r * 32 + lane];
            acc_edge(acc, cf, v);
        }
    }
    ((float4*)g_agg)[(size_t)gw * 32 + lane] = acc;
}

// ---------------------------------------------------------------------------
// K10: fused out = relu(agg @ W) . lin_w + lin_b — packed f32x2 FMA.
// ---------------------------------------------------------------------------
__global__ void final_kernel(const float* __restrict__ lin_w, const float* __restrict__ lin_b,
                             float* __restrict__ out, int n) {
    extern __shared__ float smem[];
    float* sW = smem;                 // F*F
    float* sLin = smem + F * F;       // F
    float* sAgg = sLin + F;           // 8 warps * TNODES * F

    int tid = threadIdx.x;  // 256
    for (int i = tid; i < F * F / 4; i += blockDim.x)
        ((float4*)sW)[i] = ((const float4*)g_W)[i];
    if (tid < F) sLin[tid] = lin_w[tid];
    __syncthreads();

    int warp = tid >> 5, lane = tid & 31;
    int node0 = (blockIdx.x * 8 + warp) * TNODES;
    float* sa = sAgg + warp * (TNODES * F);

#pragma unroll
    for (int nn = 0; nn < TNODES; nn++) {
        int node = node0 + nn;
        float4 v = make_float4(0.f, 0.f, 0.f, 0.f);
        if (node < n) v = ((const float4*)g_agg)[(size_t)node * 32 + lane];
        ((float4*)(sa + nn * F))[lane] = v;
    }
    __syncwarp();

    unsigned long long acc[TNODES][2];
#pragma unroll
    for (int nn = 0; nn < TNODES; nn++) { acc[nn][0] = 0ULL; acc[nn][1] = 0ULL; }

    int col = lane * 4;
    for (int k0 = 0; k0 < F; k0 += 4) {
        ulonglong2 w0 = *(const ulonglong2*)&sW[(k0 + 0) * F + col];
        ulonglong2 w1 = *(const ulonglong2*)&sW[(k0 + 1) * F + col];
        ulonglong2 w2 = *(const ulonglong2*)&sW[(k0 + 2) * F + col];
        ulonglong2 w3 = *(const ulonglong2*)&sW[(k0 + 3) * F + col];
#pragma unroll
        for (int nn = 0; nn < TNODES; nn++) {
            float4 a = *(const float4*)&sa[nn * F + k0];
            unsigned long long ax = pack2(a.x), ay = pack2(a.y),
                               az = pack2(a.z), aw = pack2(a.w);
            acc[nn][0] = ffma2(ax, w0.x, acc[nn][0]);
            acc[nn][0] = ffma2(ay, w1.x, acc[nn][0]);
            acc[nn][0] = ffma2(az, w2.x, acc[nn][0]);
            acc[nn][0] = ffma2(aw, w3.x, acc[nn][0]);
            acc[nn][1] = ffma2(ax, w0.y, acc[nn][1]);
            acc[nn][1] = ffma2(ay, w1.y, acc[nn][1]);
            acc[nn][1] = ffma2(az, w2.y, acc[nn][1]);
            acc[nn][1] = ffma2(aw, w3.y, acc[nn][1]);
        }
    }

    float lw0 = sLin[col], lw1 = sLin[col + 1], lw2 = sLin[col + 2], lw3 = sLin[col + 3];
    float bias = lin_b[0];
#pragma unroll
    for (int nn = 0; nn < TNODES; nn++) {
        float2 h01 = unpack2(acc[nn][0]);
        float2 h23 = unpack2(acc[nn][1]);
        float s = fmaxf(h01.x, 0.f) * lw0 + fmaxf(h01.y, 0.f) * lw1 +
                  fmaxf(h23.x, 0.f) * lw2 + fmaxf(h23.y, 0.f) * lw3;
#pragma unroll
        for (int off = 16; off; off >>= 1)
            s += __shfl_xor_sync(0xffffffffu, s, off);
        int node = node0 + nn;
        if (lane == 0 && node < n) out[node] = s + bias;
    }
}

// ---------------------------------------------------------------------------
extern "C" void kernel_launch(void* const* d_in, const int* in_sizes, int n_in,
                              void* d_out, int out_size) {
    const float* x     = (const float*)d_in[0];
    const int*   ei    = (const int*)d_in[1];
    const float* ew    = (const float*)d_in[2];
    const float* W0    = (const float*)d_in[3];
    const float* w_ih  = (const float*)d_in[4];
    const float* w_hh  = (const float*)d_in[5];
    const float* b_ih  = (const float*)d_in[6];
    const float* b_hh  = (const float*)d_in[7];
    const float* lin_w = (const float*)d_in[8];
    const float* lin_b = (const float*)d_in[9];
    float* out = (float*)d_out;

    int n = in_sizes[0] / F;
    int E = in_sizes[2];
    int nb = (n + 255) / 256;

    evolve_kernel<<<F, 3 * F>>>(W0, w_ih, w_hh, b_ih, b_hh);
    x2h_kernel<<<(n * 32 + 255) / 256, 256>>>(x, n);
    init_kernel<<<nb, 256>>>(n);
    deg_hist<<<(E + 255) / 256, 256>>>(ei, ew, E);
    scan_part<<<nb, 256>>>(n);          // also finishes dinv
    scan_top<<<1, 32>>>(nb);
    scan_final<<<nb, 256>>>(n);
    place_kernel<<<(E + 255) / 256, 256>>>(ei, ew, E);
    agg_kernel<<<(n * 32 + 255) / 256, 256>>>(x, n);  // warp per node

    int warps = (n + TNODES - 1) / TNODES;
    int blocks = (warps + 7) / 8;
    size_t smem = (size_t)(F * F + F + 8 * TNODES * F) * sizeof(float);
    cudaFuncSetAttribute(final_kernel, cudaFuncAttributeMaxDynamicSharedMemorySize, (int)smem);
    final_kernel<<<blocks, 256, smem>>>(lin_w, lin_b, out, n);
}

// round 8
// speedup vs baseline: 1.1552x; 1.0727x over previous
#include <cuda_runtime.h>
#include <cuda_fp16.h>

#define F 128
#define N_MAX 100352
#define E_MAX 1600000
#define TNODES 8
#define NB_MAX ((N_MAX + 255) / 256)

// Scratch (device globals — allocation-free per harness rules)
__device__ float g_W[F * F];
__device__ float g_dinv[N_MAX];
__device__ unsigned g_dc[2 * N_MAX];   // interleaved (deg:f32, count:u32) per node
__device__ int   g_count[N_MAX];
__device__ int   g_offset[N_MAX];
__device__ int   g_cursor[N_MAX];
__device__ int   g_bsum[NB_MAX];
__device__ unsigned long long g_edge[E_MAX];   // packed (row:int32 | coef:f32<<32)
__device__ __half g_xh[(size_t)N_MAX * F];     // fp16 copy of x for gather
__device__ float g_agg[(size_t)N_MAX * F];

// ---------------------------------------------------------------------------
// Packed fp32x2 helpers (sm_103a dual-lane fp32 pipe; full fp32 numerics)
// ---------------------------------------------------------------------------
__device__ __forceinline__ unsigned long long ffma2(unsigned long long a,
                                                    unsigned long long b,
                                                    unsigned long long c) {
    unsigned long long r;
    asm("fma.rn.f32x2 %0, %1, %2, %3;" : "=l"(r) : "l"(a), "l"(b), "l"(c));
    return r;
}
__device__ __forceinline__ unsigned long long pack2(float x) {
    unsigned long long r;
    asm("mov.b64 %0, {%1, %1};" : "=l"(r) : "f"(x));
    return r;
}
__device__ __forceinline__ float2 unpack2(unsigned long long v) {
    float2 f;
    asm("mov.b64 {%0, %1}, %2;" : "=f"(f.x), "=f"(f.y) : "l"(v));
    return f;
}

// ---------------------------------------------------------------------------
// K-side-1: evolve weight — one GRU step on W0 (batch = F rows).
// ---------------------------------------------------------------------------
__global__ void evolve_kernel(const float* __restrict__ W0,
                              const float* __restrict__ w_ih,
                              const float* __restrict__ w_hh,
                              const float* __restrict__ b_ih,
                              const float* __restrict__ b_hh) {
    __shared__ float s_row[F];
    __shared__ float s_gi[3 * F];
    __shared__ float s_gh[3 * F];
    int i = blockIdx.x;
    int j = threadIdx.x;  // 0..383
    if (j < F) s_row[j] = W0[i * F + j];
    __syncthreads();

    float gi = b_ih[j], gh = b_hh[j];
    const float* wi = w_ih + j * F;
    const float* wh = w_hh + j * F;
#pragma unroll 8
    for (int k = 0; k < F; k++) {
        float a = s_row[k];
        gi += a * wi[k];
        gh += a * wh[k];
    }
    s_gi[j] = gi;
    s_gh[j] = gh;
    __syncthreads();

    if (j < F) {
        float r = 1.f / (1.f + expf(-(s_gi[j] + s_gh[j])));
        float z = 1.f / (1.f + expf(-(s_gi[F + j] + s_gh[F + j])));
        float nn = tanhf(s_gi[2 * F + j] + r * s_gh[2 * F + j]);
        g_W[i * F + j] = (1.f - z) * nn + z * s_row[j];
    }
}

// ---------------------------------------------------------------------------
// K-side-2: x -> fp16 copy (for low-traffic gather)
// ---------------------------------------------------------------------------
__global__ void x2h_kernel(const float* __restrict__ x, int n) {
    int idx = blockIdx.x * blockDim.x + threadIdx.x;  // over n*32 float4s
    if (idx >= n * 32) return;
    float4 v = ((const float4*)x)[idx];
    __half2 a = __floats2half2_rn(v.x, v.y);
    __half2 b = __floats2half2_rn(v.z, v.w);
    uint2 o;
    o.x = *(unsigned int*)&a;
    o.y = *(unsigned int*)&b;
    ((uint2*)g_xh)[idx] = o;
}

// ---------------------------------------------------------------------------
// K1: degree + histogram, both atomics into the SAME 8B pair (one sector)
// ---------------------------------------------------------------------------
__global__ void deg_hist(const int* __restrict__ ei, const float* __restrict__ ew, int E) {
    int e = blockIdx.x * blockDim.x + threadIdx.x;
    if (e < E) {
        int c = ei[E + e];
        atomicAdd((float*)&g_dc[2 * c], ew[e]);
        atomicAdd(&g_dc[2 * c + 1], 1u);
    }
}

// ---------------------------------------------------------------------------
// K2-K4: dinv = rsqrt(1 + deg); count -> exclusive scan -> g_offset/g_cursor
// ---------------------------------------------------------------------------
__global__ void scan_part(int n) {
    __shared__ int s[256];
    int i = blockIdx.x * 256 + threadIdx.x;
    int cnt = 0;
    if (i < n) {
        uint2 p = ((const uint2*)g_dc)[i];
        float deg = __uint_as_float(p.x) + 1.0f;  // +1 self loop
        g_dinv[i] = rsqrtf(deg);
        cnt = (int)p.y;
        g_count[i] = cnt;
    }
    s[threadIdx.x] = cnt;
    __syncthreads();
    for (int st = 128; st; st >>= 1) {
        if (threadIdx.x < st) s[threadIdx.x] += s[threadIdx.x + st];
        __syncthreads();
    }
    if (threadIdx.x == 0) g_bsum[blockIdx.x] = s[0];
}

__global__ void scan_top(int nb) {
    __shared__ int s[512];
    int t = threadIdx.x;
    s[t] = (t < nb) ? g_bsum[t] : 0;
    __syncthreads();
    // inclusive Hillis-Steele, then shift to exclusive on write-back
    for (int st = 1; st < 512; st <<= 1) {
        int add = (t >= st) ? s[t - st] : 0;
        __syncthreads();
        s[t] += add;
        __syncthreads();
    }
    if (t < nb) g_bsum[t] = (t == 0) ? 0 : s[t - 1];
}

__global__ void scan_final(int n) {
    __shared__ int s[257];
    int i = blockIdx.x * 256 + threadIdx.x;
    int v = (i < n) ? g_count[i] : 0;
    s[threadIdx.x + 1] = v;
    if (threadIdx.x == 0) s[0] = 0;
    __syncthreads();
    for (int st = 1; st < 256; st <<= 1) {
        int add = (threadIdx.x >= st) ? s[threadIdx.x - st] : 0;
        __syncthreads();
        s[threadIdx.x] += add;
        __syncthreads();
    }
    if (i < n) {
        int off = g_bsum[blockIdx.x] + s[threadIdx.x];
        g_offset[i] = off;
        g_cursor[i] = off;
    }
}

// ---------------------------------------------------------------------------
// K5: place edges into target-sorted order; one packed 8B record per edge
// ---------------------------------------------------------------------------
__global__ void place_kernel(const int* __restrict__ ei, const float* __restrict__ ew, int E) {
    int e = blockIdx.x * blockDim.x + threadIdx.x;
    if (e >= E) return;
    int r = ei[e];
    int c = ei[E + e];
    int p = atomicAdd(&g_cursor[c], 1);
    float cf = g_dinv[r] * ew[e] * g_dinv[c];
    g_edge[p] = (unsigned long long)(unsigned int)r |
                ((unsigned long long)__float_as_uint(cf) << 32);
}

// ---------------------------------------------------------------------------
// K6: aggregate — warp per node, fp16 gather (256B/edge), fp32 accumulate.
// ---------------------------------------------------------------------------
__device__ __forceinline__ void acc_edge(float4& acc, float cf, uint2 v) {
    float2 a = __half22float2(*(__half2*)&v.x);
    float2 b = __half22float2(*(__half2*)&v.y);
    acc.x += cf * a.x;
    acc.y += cf * a.y;
    acc.z += cf * b.x;
    acc.w += cf * b.y;
}

__global__ void agg_kernel(const float* __restrict__ x, int n) {
    int gw = (int)((blockIdx.x * (unsigned)blockDim.x + threadIdx.x) >> 5);
    int lane = threadIdx.x & 31;
    if (gw >= n) return;

    int off = g_offset[gw];
    int cnt = g_count[gw];
    float dc = g_dinv[gw];
    float sc = dc * dc;

    float4 acc = ((const float4*)x)[(size_t)gw * 32 + lane];
    acc.x *= sc; acc.y *= sc; acc.z *= sc; acc.w *= sc;

    const uint2* x2 = (const uint2*)g_xh;  // row = 32 uint2 (128 halves)

    for (int base = 0; base < cnt; base += 32) {
        int m = min(32, cnt - base);
        unsigned long long rec = 0ULL;
        if (lane < m) rec = __ldg(&g_edge[off + base + lane]);
        int j = 0;
        for (; j + 4 <= m; j += 4) {
            unsigned long long q0 = __shfl_sync(0xffffffffu, rec, j + 0);
            unsigned long long q1 = __shfl_sync(0xffffffffu, rec, j + 1);
            unsigned long long q2 = __shfl_sync(0xffffffffu, rec, j + 2);
            unsigned long long q3 = __shfl_sync(0xffffffffu, rec, j + 3);
            int r0 = (int)(unsigned int)q0, r1 = (int)(unsigned int)q1;
            int r2 = (int)(unsigned int)q2, r3 = (int)(unsigned int)q3;
            float c0 = __uint_as_float((unsigned int)(q0 >> 32));
            float c1 = __uint_as_float((unsigned int)(q1 >> 32));
            float c2 = __uint_as_float((unsigned int)(q2 >> 32));
            float c3 = __uint_as_float((unsigned int)(q3 >> 32));
            uint2 v0 = x2[(size_t)r0 * 32 + lane];
            uint2 v1 = x2[(size_t)r1 * 32 + lane];
            uint2 v2 = x2[(size_t)r2 * 32 + lane];
            uint2 v3 = x2[(size_t)r3 * 32 + lane];
            acc_edge(acc, c0, v0);
            acc_edge(acc, c1, v1);
            acc_edge(acc, c2, v2);
            acc_edge(acc, c3, v3);
        }
        for (; j < m; j++) {
            unsigned long long q = __shfl_sync(0xffffffffu, rec, j);
            int r = (int)(unsigned int)q;
            float cf = __uint_as_float((unsigned int)(q >> 32));
            uint2 v = x2[(size_t)r * 32 + lane];
            acc_edge(acc, cf, v);
        }
    }
    ((float4*)g_agg)[(size_t)gw * 32 + lane] = acc;
}

// ---------------------------------------------------------------------------
// K7: fused out = relu(agg @ W) . lin_w + lin_b — packed f32x2 FMA.
// ---------------------------------------------------------------------------
__global__ void final_kernel(const float* __restrict__ lin_w, const float* __restrict__ lin_b,
                             float* __restrict__ out, int n) {
    extern __shared__ float smem[];
    float* sW = smem;                 // F*F
    float* sLin = smem + F * F;       // F
    float* sAgg = sLin + F;           // 8 warps * TNODES * F

    int tid = threadIdx.x;  // 256
    for (int i = tid; i < F * F / 4; i += blockDim.x)
        ((float4*)sW)[i] = ((const float4*)g_W)[i];
    if (tid < F) sLin[tid] = lin_w[tid];
    __syncthreads();

    int warp = tid >> 5, lane = tid & 31;
    int node0 = (blockIdx.x * 8 + warp) * TNODES;
    float* sa = sAgg + warp * (TNODES * F);

#pragma unroll
    for (int nn = 0; nn < TNODES; nn++) {
        int node = node0 + nn;
        float4 v = make_float4(0.f, 0.f, 0.f, 0.f);
        if (node < n) v = ((const float4*)g_agg)[(size_t)node * 32 + lane];
        ((float4*)(sa + nn * F))[lane] = v;
    }
    __syncwarp();

    unsigned long long acc[TNODES][2];
#pragma unroll
    for (int nn = 0; nn < TNODES; nn++) { acc[nn][0] = 0ULL; acc[nn][1] = 0ULL; }

    int col = lane * 4;
    for (int k0 = 0; k0 < F; k0 += 4) {
        ulonglong2 w0 = *(const ulonglong2*)&sW[(k0 + 0) * F + col];
        ulonglong2 w1 = *(const ulonglong2*)&sW[(k0 + 1) * F + col];
        ulonglong2 w2 = *(const ulonglong2*)&sW[(k0 + 2) * F + col];
        ulonglong2 w3 = *(const ulonglong2*)&sW[(k0 + 3) * F + col];
#pragma unroll
        for (int nn = 0; nn < TNODES; nn++) {
            float4 a = *(const float4*)&sa[nn * F + k0];
            unsigned long long ax = pack2(a.x), ay = pack2(a.y),
                               az = pack2(a.z), aw = pack2(a.w);
            acc[nn][0] = ffma2(ax, w0.x, acc[nn][0]);
            acc[nn][0] = ffma2(ay, w1.x, acc[nn][0]);
            acc[nn][0] = ffma2(az, w2.x, acc[nn][0]);
            acc[nn][0] = ffma2(aw, w3.x, acc[nn][0]);
            acc[nn][1] = ffma2(ax, w0.y, acc[nn][1]);
            acc[nn][1] = ffma2(ay, w1.y, acc[nn][1]);
            acc[nn][1] = ffma2(az, w2.y, acc[nn][1]);
            acc[nn][1] = ffma2(aw, w3.y, acc[nn][1]);
        }
    }

    float lw0 = sLin[col], lw1 = sLin[col + 1], lw2 = sLin[col + 2], lw3 = sLin[col + 3];
    float bias = lin_b[0];
#pragma unroll
    for (int nn = 0; nn < TNODES; nn++) {
        float2 h01 = unpack2(acc[nn][0]);
        float2 h23 = unpack2(acc[nn][1]);
        float s = fmaxf(h01.x, 0.f) * lw0 + fmaxf(h01.y, 0.f) * lw1 +
                  fmaxf(h23.x, 0.f) * lw2 + fmaxf(h23.y, 0.f) * lw3;
#pragma unroll
        for (int off = 16; off; off >>= 1)
            s += __shfl_xor_sync(0xffffffffu, s, off);
        int node = node0 + nn;
        if (lane == 0 && node < n) out[node] = s + bias;
    }
}

// ---------------------------------------------------------------------------
extern "C" void kernel_launch(void* const* d_in, const int* in_sizes, int n_in,
                              void* d_out, int out_size) {
    const float* x     = (const float*)d_in[0];
    const int*   ei    = (const int*)d_in[1];
    const float* ew    = (const float*)d_in[2];
    const float* W0    = (const float*)d_in[3];
    const float* w_ih  = (const float*)d_in[4];
    const float* w_hh  = (const float*)d_in[5];
    const float* b_ih  = (const float*)d_in[6];
    const float* b_hh  = (const float*)d_in[7];
    const float* lin_w = (const float*)d_in[8];
    const float* lin_b = (const float*)d_in[9];
    float* out = (float*)d_out;

    int n = in_sizes[0] / F;
    int E = in_sizes[2];
    int nb = (n + 255) / 256;

    // Fork-join: side stream runs evolve + x2h concurrently with the
    // deg/scan/place chain on the main (capture-origin) stream.
    cudaStream_t s2;
    cudaStreamCreateWithFlags(&s2, cudaStreamNonBlocking);
    cudaEvent_t evFork, evJoin;
    cudaEventCreateWithFlags(&evFork, cudaEventDisableTiming);
    cudaEventCreateWithFlags(&evJoin, cudaEventDisableTiming);

    cudaEventRecord(evFork, 0);
    cudaStreamWaitEvent(s2, evFork, 0);
    evolve_kernel<<<F, 3 * F, 0, s2>>>(W0, w_ih, w_hh, b_ih, b_hh);
    x2h_kernel<<<(n * 32 + 255) / 256, 256, 0, s2>>>(x, n);
    cudaEventRecord(evJoin, s2);

    // Main chain
    void* dc_ptr = nullptr;
    cudaGetSymbolAddress(&dc_ptr, g_dc);
    cudaMemsetAsync(dc_ptr, 0, (size_t)2 * N_MAX * sizeof(unsigned), 0);
    deg_hist<<<(E + 255) / 256, 256>>>(ei, ew, E);
    scan_part<<<nb, 256>>>(n);
    scan_top<<<1, 512>>>(nb);
    scan_final<<<nb, 256>>>(n);
    place_kernel<<<(E + 255) / 256, 256>>>(ei, ew, E);

    cudaStreamWaitEvent(0, evJoin, 0);  // join side stream before agg/final
    agg_kernel<<<(n * 32 + 255) / 256, 256>>>(x, n);  // warp per node

    int warps = (n + TNODES - 1) / TNODES;
    int blocks = (warps + 7) / 8;
    size_t smem = (size_t)(F * F + F + 8 * TNODES * F) * sizeof(float);
    cudaFuncSetAttribute(final_kernel, cudaFuncAttributeMaxDynamicSharedMemorySize, (int)smem);
    final_kernel<<<blocks, 256, smem>>>(lin_w, lin_b, out, n);
}